// round 1
// baseline (speedup 1.0000x reference)
#include <cuda_runtime.h>
#include <cstdint>

// Problem dims (fixed by reference)
#define NB   32
#define H0   512
#define W0   512
#define H1   256
#define W1   256
#define H2   128
#define W2   128
#define MPIX (H2*W2)   // 16384
#define KC   4         // clusters
#define DC   16        // feature dim

// Scratch (device globals: allocation-free)
__device__ float g_h1[(size_t)NB * H1 * W1 * 4];     // NHWC, 33.5 MB
__device__ float g_h2[(size_t)NB * MPIX * 16];       // NHWC (pixel-major), 33.5 MB

// ---------------------------------------------------------------------------
// Kernel 1: conv1(3->4, 3x3 SAME) + ReLU + 2x2 avgpool, NCHW in -> NHWC out
// One thread = one pooled output pixel, all 4 output channels.
// grid = (H1, NB), block = W1 (256)
// ---------------------------------------------------------------------------
__global__ void __launch_bounds__(W1) conv1_pool_kernel(
    const float* __restrict__ x,
    const float* __restrict__ w,   // (4,3,3,3)
    const float* __restrict__ b)   // (4,)
{
    __shared__ float sw[4 * 3 * 3 * 3];
    __shared__ float sb[4];
    const int tid = threadIdx.x;
    if (tid < 108) sw[tid] = w[tid];
    if (tid < 4)   sb[tid] = b[tid];
    __syncthreads();

    const int px = tid;
    const int py = blockIdx.x;
    const int n  = blockIdx.y;
    const int y0 = 2 * py - 1;
    const int x0 = 2 * px - 1;

    float p[3][4][4];
    const float* xn = x + (size_t)n * 3 * H0 * W0;
#pragma unroll
    for (int c = 0; c < 3; ++c) {
        const float* xc = xn + (size_t)c * H0 * W0;
#pragma unroll
        for (int dy = 0; dy < 4; ++dy) {
            const int y = y0 + dy;
            const bool yok = ((unsigned)y < (unsigned)H0);
#pragma unroll
            for (int dx = 0; dx < 4; ++dx) {
                const int xx = x0 + dx;
                p[c][dy][dx] = (yok && (unsigned)xx < (unsigned)W0)
                                   ? __ldg(xc + (size_t)y * W0 + xx) : 0.0f;
            }
        }
    }

    float res[4];
#pragma unroll
    for (int co = 0; co < 4; ++co) {
        const float bb = sb[co];
        float s00 = bb, s01 = bb, s10 = bb, s11 = bb;
#pragma unroll
        for (int c = 0; c < 3; ++c)
#pragma unroll
            for (int ky = 0; ky < 3; ++ky)
#pragma unroll
                for (int kx = 0; kx < 3; ++kx) {
                    const float wv = sw[((co * 3 + c) * 3 + ky) * 3 + kx];
                    s00 = fmaf(p[c][ky    ][kx    ], wv, s00);
                    s01 = fmaf(p[c][ky    ][kx + 1], wv, s01);
                    s10 = fmaf(p[c][ky + 1][kx    ], wv, s10);
                    s11 = fmaf(p[c][ky + 1][kx + 1], wv, s11);
                }
        res[co] = 0.25f * (fmaxf(s00, 0.f) + fmaxf(s01, 0.f) +
                           fmaxf(s10, 0.f) + fmaxf(s11, 0.f));
    }

    float4* o = (float4*)(g_h1 + (((size_t)n * H1 + py) * W1 + px) * 4);
    *o = make_float4(res[0], res[1], res[2], res[3]);
}

// ---------------------------------------------------------------------------
// Kernel 2: conv2(4->16, 3x3 SAME) + ReLU + 2x2 avgpool, NHWC in -> NHWC out
// One thread = one pooled output pixel, all 16 output channels.
// grid = (H2, NB), block = W2 (128)
// ---------------------------------------------------------------------------
__global__ void __launch_bounds__(W2) conv2_pool_kernel(
    const float* __restrict__ w,   // (16,4,3,3)
    const float* __restrict__ b)   // (16,)
{
    __shared__ float sw[16 * 4 * 3 * 3];  // 576
    __shared__ float sb[16];
    const int tid = threadIdx.x;
    for (int i = tid; i < 576; i += W2) sw[i] = w[i];
    if (tid < 16) sb[tid] = b[tid];
    __syncthreads();

    const int px = tid;
    const int py = blockIdx.x;
    const int n  = blockIdx.y;
    const int y0 = 2 * py - 1;
    const int x0 = 2 * px - 1;

    // 4x4 pixel patch x 4 input channels (NHWC -> float4 per pixel)
    float p[4][4][4];  // [dy][dx][ci]
    const float* hn = g_h1 + (size_t)n * H1 * W1 * 4;
#pragma unroll
    for (int dy = 0; dy < 4; ++dy) {
        const int y = y0 + dy;
        const bool yok = ((unsigned)y < (unsigned)H1);
#pragma unroll
        for (int dx = 0; dx < 4; ++dx) {
            const int xx = x0 + dx;
            float4 v = make_float4(0.f, 0.f, 0.f, 0.f);
            if (yok && (unsigned)xx < (unsigned)W1)
                v = *(const float4*)(hn + ((size_t)y * W1 + xx) * 4);
            p[dy][dx][0] = v.x; p[dy][dx][1] = v.y;
            p[dy][dx][2] = v.z; p[dy][dx][3] = v.w;
        }
    }

    float res[16];
#pragma unroll 4
    for (int co = 0; co < 16; ++co) {
        const float bb = sb[co];
        float s00 = bb, s01 = bb, s10 = bb, s11 = bb;
#pragma unroll
        for (int ci = 0; ci < 4; ++ci)
#pragma unroll
            for (int ky = 0; ky < 3; ++ky)
#pragma unroll
                for (int kx = 0; kx < 3; ++kx) {
                    const float wv = sw[((co * 4 + ci) * 3 + ky) * 3 + kx];
                    s00 = fmaf(p[ky    ][kx    ][ci], wv, s00);
                    s01 = fmaf(p[ky    ][kx + 1][ci], wv, s01);
                    s10 = fmaf(p[ky + 1][kx    ][ci], wv, s10);
                    s11 = fmaf(p[ky + 1][kx + 1][ci], wv, s11);
                }
        res[co] = 0.25f * (fmaxf(s00, 0.f) + fmaxf(s01, 0.f) +
                           fmaxf(s10, 0.f) + fmaxf(s11, 0.f));
    }

    float* o = g_h2 + ((size_t)n * MPIX + (size_t)py * W2 + px) * 16;
    float4* o4 = (float4*)o;
#pragma unroll
    for (int q = 0; q < 4; ++q)
        o4[q] = make_float4(res[q*4+0], res[q*4+1], res[q*4+2], res[q*4+3]);
}

// ---------------------------------------------------------------------------
// Kernel 3: NetVLAD + intra-norm + global-norm + linear head. One block/image.
// grid = NB, block = 512
// ---------------------------------------------------------------------------
#define K3_THREADS 512
#define K3_WARPS   (K3_THREADS / 32)

__global__ void __launch_bounds__(K3_THREADS) netvlad_head_kernel(
    const float* __restrict__ aw,    // (4,16) assign_w
    const float* __restrict__ ab,    // (4,)   assign_b
    const float* __restrict__ cent,  // (4,16)
    const float* __restrict__ lw,    // (7,64)
    const float* __restrict__ lb,    // (7,)
    float* __restrict__ out)         // (NB,7)
{
    const int n   = blockIdx.x;
    const int tid = threadIdx.x;
    const int lane = tid & 31;
    const int wrp  = tid >> 5;

    __shared__ float s_aw[64];
    __shared__ float s_ab[4];
    if (tid < 64) s_aw[tid] = aw[tid];
    if (tid < 4)  s_ab[tid] = ab[tid];
    __syncthreads();

    // 64 vlad accumulators [k*16+c] + 4 assignment sums
    float acc[68];
#pragma unroll
    for (int i = 0; i < 68; ++i) acc[i] = 0.0f;

    const float* base = g_h2 + (size_t)n * MPIX * 16;
    for (int m = tid; m < MPIX; m += K3_THREADS) {
        const float4* xp = (const float4*)(base + (size_t)m * 16);
        float xv[16];
#pragma unroll
        for (int q = 0; q < 4; ++q) {
            float4 v = xp[q];
            xv[q*4+0] = v.x; xv[q*4+1] = v.y; xv[q*4+2] = v.z; xv[q*4+3] = v.w;
        }
        float lg[4];
#pragma unroll
        for (int k = 0; k < 4; ++k) {
            float s = s_ab[k];
#pragma unroll
            for (int c = 0; c < 16; ++c)
                s = fmaf(xv[c], s_aw[k * 16 + c], s);
            lg[k] = s;
        }
        float mx = fmaxf(fmaxf(lg[0], lg[1]), fmaxf(lg[2], lg[3]));
        float e[4], es = 0.0f;
#pragma unroll
        for (int k = 0; k < 4; ++k) { e[k] = __expf(lg[k] - mx); es += e[k]; }
        const float inv = __fdividef(1.0f, es);
#pragma unroll
        for (int k = 0; k < 4; ++k) {
            const float a = e[k] * inv;
            acc[64 + k] += a;
#pragma unroll
            for (int c = 0; c < 16; ++c)
                acc[k * 16 + c] = fmaf(a, xv[c], acc[k * 16 + c]);
        }
    }

    // warp reduction of all 68 values
#pragma unroll
    for (int off = 16; off > 0; off >>= 1)
#pragma unroll
        for (int i = 0; i < 68; ++i)
            acc[i] += __shfl_down_sync(0xffffffffu, acc[i], off);

    __shared__ float red[K3_WARPS][68];
    if (lane == 0)
#pragma unroll
        for (int i = 0; i < 68; ++i) red[wrp][i] = acc[i];
    __syncthreads();

    __shared__ float sv[68];
    if (tid < 68) {
        float s = 0.0f;
#pragma unroll
        for (int ww = 0; ww < K3_WARPS; ++ww) s += red[ww][tid];
        sv[tid] = s;
    }
    __syncthreads();

    // finalize: vlad = sum - asum*cent ; intra L2 over c ; global L2 ; linear
    __shared__ float v2[64];
    __shared__ float nk[4];
    __shared__ float gn;
    if (tid < 64) {
        const int k = tid >> 4;
        v2[tid] = sv[tid] - sv[64 + k] * __ldg(cent + tid);
    }
    __syncthreads();
    if (tid < 4) {
        float s = 0.0f;
#pragma unroll
        for (int c = 0; c < 16; ++c) { const float v = v2[tid * 16 + c]; s = fmaf(v, v, s); }
        nk[tid] = fmaxf(sqrtf(s), 1e-12f);
    }
    __syncthreads();
    if (tid < 64) v2[tid] = v2[tid] / nk[tid >> 4];
    __syncthreads();
    if (tid == 0) {
        float s = 0.0f;
#pragma unroll
        for (int i = 0; i < 64; ++i) s = fmaf(v2[i], v2[i], s);
        gn = fmaxf(sqrtf(s), 1e-12f);
    }
    __syncthreads();
    if (tid < 7) {
        float s = __ldg(lb + tid);
        const float ig = 1.0f / gn;
#pragma unroll
        for (int i = 0; i < 64; ++i)
            s = fmaf(v2[i] * ig, __ldg(lw + tid * 64 + i), s);
        out[n * 7 + tid] = s;
    }
}

// ---------------------------------------------------------------------------
extern "C" void kernel_launch(void* const* d_in, const int* in_sizes, int n_in,
                              void* d_out, int out_size)
{
    (void)in_sizes; (void)n_in; (void)out_size;
    const float* x       = (const float*)d_in[0];
    const float* conv1_w = (const float*)d_in[1];
    const float* conv1_b = (const float*)d_in[2];
    const float* conv2_w = (const float*)d_in[3];
    const float* conv2_b = (const float*)d_in[4];
    const float* cent    = (const float*)d_in[5];
    const float* aw      = (const float*)d_in[6];
    const float* ab      = (const float*)d_in[7];
    const float* lw      = (const float*)d_in[8];
    const float* lb      = (const float*)d_in[9];
    float* out = (float*)d_out;

    dim3 g1(H1, NB); conv1_pool_kernel<<<g1, W1>>>(x, conv1_w, conv1_b);
    dim3 g2(H2, NB); conv2_pool_kernel<<<g2, W2>>>(conv2_w, conv2_b);
    netvlad_head_kernel<<<NB, K3_THREADS>>>(aw, ab, cent, lw, lb, out);
}

// round 2
// speedup vs baseline: 1.0767x; 1.0767x over previous
#include <cuda_runtime.h>
#include <cstdint>

// Problem dims (fixed by reference)
#define NB   32
#define H0   512
#define W0   512
#define H1   256
#define W1   256
#define H2   128
#define W2   128
#define MPIX (H2*W2)   // 16384
#define KC   4
#define DC   16
#define K3_CHUNKS 8

// Scratch (device globals: allocation-free)
__device__ float g_h1[(size_t)NB * H1 * W1 * 4];   // NHWC
__device__ float g_h2[(size_t)NB * MPIX * 16];     // NHWC pixel-major
__device__ float g_part[NB][K3_CHUNKS][68];        // netvlad partials

// ---- packed f32x2 helpers (Blackwell FFMA2) --------------------------------
typedef unsigned long long u64t;
__device__ __forceinline__ u64t pack2(float lo, float hi) {
    u64t r; asm("mov.b64 %0,{%1,%2};" : "=l"(r) : "f"(lo), "f"(hi)); return r;
}
__device__ __forceinline__ void fma2(u64t& d, u64t a, u64t b) {
    asm("fma.rn.f32x2 %0,%1,%2,%0;" : "+l"(d) : "l"(a), "l"(b));
}
__device__ __forceinline__ float2 unpack2(u64t v) {
    float2 r; asm("mov.b64 {%0,%1},%2;" : "=f"(r.x), "=f"(r.y) : "l"(v)); return r;
}

// ---------------------------------------------------------------------------
// Kernel 1: conv1(3->4) + ReLU + 2x2 avgpool, NCHW -> NHWC, FFMA2 packed
// grid = (H1, NB), block = 256
// ---------------------------------------------------------------------------
__global__ void __launch_bounds__(W1) conv1_pool_kernel(
    const float* __restrict__ x,
    const float* __restrict__ w,   // (4,3,3,3)
    const float* __restrict__ b)
{
    __shared__ u64t  sw2[108];
    __shared__ float sb[4];
    const int tid = threadIdx.x;
    if (tid < 108) { const float wv = w[tid]; sw2[tid] = pack2(wv, wv); }
    if (tid < 4)   sb[tid] = b[tid];
    __syncthreads();

    const int px = tid;
    const int py = blockIdx.x;
    const int n  = blockIdx.y;
    const int y0 = 2 * py - 1;
    const int x0 = 2 * px - 1;

    // accT[co]=(s00,s01), accB[co]=(s10,s11)
    u64t accT[4], accB[4];
#pragma unroll
    for (int co = 0; co < 4; ++co) { const u64t b2 = pack2(sb[co], sb[co]); accT[co] = b2; accB[co] = b2; }

    const float* xn = x + (size_t)n * 3 * H0 * W0;
#pragma unroll
    for (int c = 0; c < 3; ++c) {
        const float* xc = xn + (size_t)c * H0 * W0;
        float p[4][4];
#pragma unroll
        for (int dy = 0; dy < 4; ++dy) {
            const int y = y0 + dy;
            const bool yok = ((unsigned)y < (unsigned)H0);
#pragma unroll
            for (int dx = 0; dx < 4; ++dx) {
                const int xx = x0 + dx;
                p[dy][dx] = (yok && (unsigned)xx < (unsigned)W0)
                                ? __ldg(xc + (size_t)y * W0 + xx) : 0.0f;
            }
        }
        u64t P[4][3];
#pragma unroll
        for (int dy = 0; dy < 4; ++dy)
#pragma unroll
            for (int kx = 0; kx < 3; ++kx)
                P[dy][kx] = pack2(p[dy][kx], p[dy][kx + 1]);
#pragma unroll
        for (int co = 0; co < 4; ++co)
#pragma unroll
            for (int ky = 0; ky < 3; ++ky)
#pragma unroll
                for (int kx = 0; kx < 3; ++kx) {
                    const u64t w2 = sw2[(co * 3 + c) * 9 + ky * 3 + kx];
                    fma2(accT[co], P[ky][kx], w2);
                    fma2(accB[co], P[ky + 1][kx], w2);
                }
    }

    float res[4];
#pragma unroll
    for (int co = 0; co < 4; ++co) {
        const float2 t = unpack2(accT[co]);
        const float2 bo = unpack2(accB[co]);
        res[co] = 0.25f * (fmaxf(t.x, 0.f) + fmaxf(t.y, 0.f) +
                           fmaxf(bo.x, 0.f) + fmaxf(bo.y, 0.f));
    }
    float4* o = (float4*)(g_h1 + (((size_t)n * H1 + py) * W1 + px) * 4);
    *o = make_float4(res[0], res[1], res[2], res[3]);
}

// ---------------------------------------------------------------------------
// Kernel 2: conv2(4->16) + ReLU + 2x2 avgpool, NHWC -> NHWC, FFMA2 packed
// grid = (H2, NB), block = 128
// ---------------------------------------------------------------------------
__global__ void __launch_bounds__(W2) conv2_pool_kernel(
    const float* __restrict__ w,   // (16,4,3,3)
    const float* __restrict__ b)
{
    __shared__ u64t  sw2[576];
    __shared__ float sb[16];
    const int tid = threadIdx.x;
    for (int i = tid; i < 576; i += W2) { const float wv = w[i]; sw2[i] = pack2(wv, wv); }
    if (tid < 16) sb[tid] = b[tid];
    __syncthreads();

    const int px = tid;
    const int py = blockIdx.x;
    const int n  = blockIdx.y;
    const int y0 = 2 * py - 1;
    const int x0 = 2 * px - 1;

    // packed input pairs: P[dy][kx][ci] = (p[dy][kx][ci], p[dy][kx+1][ci])
    u64t P[4][3][4];
    const float* hn = g_h1 + (size_t)n * H1 * W1 * 4;
#pragma unroll
    for (int dy = 0; dy < 4; ++dy) {
        const int y = y0 + dy;
        const bool yok = ((unsigned)y < (unsigned)H1);
        float v[4][4];
#pragma unroll
        for (int dx = 0; dx < 4; ++dx) {
            const int xx = x0 + dx;
            float4 t = make_float4(0.f, 0.f, 0.f, 0.f);
            if (yok && (unsigned)xx < (unsigned)W1)
                t = *(const float4*)(hn + ((size_t)y * W1 + xx) * 4);
            v[dx][0] = t.x; v[dx][1] = t.y; v[dx][2] = t.z; v[dx][3] = t.w;
        }
#pragma unroll
        for (int kx = 0; kx < 3; ++kx)
#pragma unroll
            for (int ci = 0; ci < 4; ++ci)
                P[dy][kx][ci] = pack2(v[kx][ci], v[kx + 1][ci]);
    }

    u64t accT[16], accB[16];
#pragma unroll
    for (int co = 0; co < 16; ++co) { const u64t b2 = pack2(sb[co], sb[co]); accT[co] = b2; accB[co] = b2; }

#pragma unroll 4
    for (int co = 0; co < 16; ++co)
#pragma unroll
        for (int ci = 0; ci < 4; ++ci)
#pragma unroll
            for (int ky = 0; ky < 3; ++ky)
#pragma unroll
                for (int kx = 0; kx < 3; ++kx) {
                    const u64t w2 = sw2[((co * 4 + ci) * 3 + ky) * 3 + kx];
                    fma2(accT[co], P[ky][kx][ci], w2);
                    fma2(accB[co], P[ky + 1][kx][ci], w2);
                }

    float res[16];
#pragma unroll
    for (int co = 0; co < 16; ++co) {
        const float2 t = unpack2(accT[co]);
        const float2 bo = unpack2(accB[co]);
        res[co] = 0.25f * (fmaxf(t.x, 0.f) + fmaxf(t.y, 0.f) +
                           fmaxf(bo.x, 0.f) + fmaxf(bo.y, 0.f));
    }
    float4* o4 = (float4*)(g_h2 + ((size_t)n * MPIX + (size_t)py * W2 + px) * 16);
#pragma unroll
    for (int q = 0; q < 4; ++q)
        o4[q] = make_float4(res[q*4+0], res[q*4+1], res[q*4+2], res[q*4+3]);
}

// ---------------------------------------------------------------------------
// Kernel 3a: NetVLAD partial accumulation. grid=(NB, K3_CHUNKS), block=256
// ---------------------------------------------------------------------------
#define K3A_THREADS 256
__global__ void __launch_bounds__(K3A_THREADS) netvlad_partial_kernel(
    const float* __restrict__ aw, const float* __restrict__ ab)
{
    const int n   = blockIdx.x;
    const int ch  = blockIdx.y;
    const int tid = threadIdx.x;
    const int lane = tid & 31;
    const int wrp  = tid >> 5;

    __shared__ float s_aw[64];
    __shared__ float s_ab[4];
    if (tid < 64) s_aw[tid] = aw[tid];
    if (tid < 4)  s_ab[tid] = ab[tid];
    __syncthreads();

    float acc[68];
#pragma unroll
    for (int i = 0; i < 68; ++i) acc[i] = 0.0f;

    const int m0 = ch * (MPIX / K3_CHUNKS);
    const int m1 = m0 + (MPIX / K3_CHUNKS);
    const float* base = g_h2 + (size_t)n * MPIX * 16;
    for (int m = m0 + tid; m < m1; m += K3A_THREADS) {
        const float4* xp = (const float4*)(base + (size_t)m * 16);
        float xv[16];
#pragma unroll
        for (int q = 0; q < 4; ++q) {
            float4 v = xp[q];
            xv[q*4+0] = v.x; xv[q*4+1] = v.y; xv[q*4+2] = v.z; xv[q*4+3] = v.w;
        }
        float lg[4];
#pragma unroll
        for (int k = 0; k < 4; ++k) {
            float s = s_ab[k];
#pragma unroll
            for (int c = 0; c < 16; ++c) s = fmaf(xv[c], s_aw[k * 16 + c], s);
            lg[k] = s;
        }
        const float mx = fmaxf(fmaxf(lg[0], lg[1]), fmaxf(lg[2], lg[3]));
        float e[4], es = 0.0f;
#pragma unroll
        for (int k = 0; k < 4; ++k) { e[k] = __expf(lg[k] - mx); es += e[k]; }
        const float inv = __fdividef(1.0f, es);
#pragma unroll
        for (int k = 0; k < 4; ++k) {
            const float a = e[k] * inv;
            acc[64 + k] += a;
#pragma unroll
            for (int c = 0; c < 16; ++c)
                acc[k * 16 + c] = fmaf(a, xv[c], acc[k * 16 + c]);
        }
    }

#pragma unroll
    for (int off = 16; off > 0; off >>= 1)
#pragma unroll
        for (int i = 0; i < 68; ++i)
            acc[i] += __shfl_down_sync(0xffffffffu, acc[i], off);

    __shared__ float red[K3A_THREADS / 32][68];
    if (lane == 0)
#pragma unroll
        for (int i = 0; i < 68; ++i) red[wrp][i] = acc[i];
    __syncthreads();
    if (tid < 68) {
        float s = 0.0f;
#pragma unroll
        for (int ww = 0; ww < K3A_THREADS / 32; ++ww) s += red[ww][tid];
        g_part[n][ch][tid] = s;
    }
}

// ---------------------------------------------------------------------------
// Kernel 3b: finalize (norms + linear). grid=NB, block=128
// ---------------------------------------------------------------------------
__global__ void __launch_bounds__(128) netvlad_final_kernel(
    const float* __restrict__ cent,
    const float* __restrict__ lw,
    const float* __restrict__ lb,
    float* __restrict__ out)
{
    const int n = blockIdx.x;
    const int tid = threadIdx.x;

    __shared__ float sv[68];
    if (tid < 68) {
        float s = 0.0f;
#pragma unroll
        for (int ch = 0; ch < K3_CHUNKS; ++ch) s += g_part[n][ch][tid];
        sv[tid] = s;
    }
    __syncthreads();

    __shared__ float v2[64];
    __shared__ float nk[4];
    __shared__ float gn;
    if (tid < 64) {
        const int k = tid >> 4;
        v2[tid] = sv[tid] - sv[64 + k] * __ldg(cent + tid);
    }
    __syncthreads();
    if (tid < 4) {
        float s = 0.0f;
#pragma unroll
        for (int c = 0; c < 16; ++c) { const float v = v2[tid * 16 + c]; s = fmaf(v, v, s); }
        nk[tid] = fmaxf(sqrtf(s), 1e-12f);
    }
    __syncthreads();
    if (tid < 64) v2[tid] = v2[tid] / nk[tid >> 4];
    __syncthreads();
    if (tid == 0) {
        float s = 0.0f;
#pragma unroll
        for (int i = 0; i < 64; ++i) s = fmaf(v2[i], v2[i], s);
        gn = fmaxf(sqrtf(s), 1e-12f);
    }
    __syncthreads();
    if (tid < 7) {
        float s = __ldg(lb + tid);
        const float ig = 1.0f / gn;
#pragma unroll
        for (int i = 0; i < 64; ++i)
            s = fmaf(v2[i] * ig, __ldg(lw + tid * 64 + i), s);
        out[n * 7 + tid] = s;
    }
}

// ---------------------------------------------------------------------------
extern "C" void kernel_launch(void* const* d_in, const int* in_sizes, int n_in,
                              void* d_out, int out_size)
{
    (void)in_sizes; (void)n_in; (void)out_size;
    const float* x       = (const float*)d_in[0];
    const float* conv1_w = (const float*)d_in[1];
    const float* conv1_b = (const float*)d_in[2];
    const float* conv2_w = (const float*)d_in[3];
    const float* conv2_b = (const float*)d_in[4];
    const float* cent    = (const float*)d_in[5];
    const float* aw      = (const float*)d_in[6];
    const float* ab      = (const float*)d_in[7];
    const float* lw      = (const float*)d_in[8];
    const float* lb      = (const float*)d_in[9];
    float* out = (float*)d_out;

    dim3 g1(H1, NB); conv1_pool_kernel<<<g1, W1>>>(x, conv1_w, conv1_b);
    dim3 g2(H2, NB); conv2_pool_kernel<<<g2, W2>>>(conv2_w, conv2_b);
    dim3 g3(NB, K3_CHUNKS); netvlad_partial_kernel<<<g3, K3A_THREADS>>>(aw, ab);
    netvlad_final_kernel<<<NB, 128>>>(cent, lw, lb, out);
}

// round 3
// speedup vs baseline: 1.4174x; 1.3164x over previous
#include <cuda_runtime.h>
#include <cstdint>

// Problem dims (fixed by reference)
#define NB   32
#define H0   512
#define W0   512
#define H1   256
#define W1   256
#define H2   128
#define W2   128
#define MPIX (H2*W2)   // 16384
#define K3_CHUNKS 8

// Scratch (device globals: allocation-free)
__device__ float g_h1[(size_t)NB * H1 * W1 * 4];   // NHWC (4ch per pixel)
__device__ float g_h2[(size_t)NB * MPIX * 16];     // NHWC pixel-major
__device__ float g_part[NB][K3_CHUNKS][68];        // netvlad partials

// ---------------------------------------------------------------------------
// Kernel 1: conv1(3->4, 3x3 SAME) + ReLU + 2x2 avgpool, NCHW -> NHWC
// One thread = one pooled pixel. Interior fast path: const-offset loads.
// grid = (H1, NB), block = 256
// ---------------------------------------------------------------------------
__global__ void __launch_bounds__(W1) conv1_pool_kernel(
    const float* __restrict__ x,
    const float* __restrict__ w,   // (4,3,3,3) co-major
    const float* __restrict__ b)
{
    __shared__ float4 sw4[27];     // [c*9+ky*3+kx] -> w over 4 co
    __shared__ float  sb[4];
    const int tid = threadIdx.x;
    if (tid < 27)
        sw4[tid] = make_float4(w[tid], w[27 + tid], w[54 + tid], w[81 + tid]);
    if (tid < 4) sb[tid] = b[tid];
    __syncthreads();

    const int px = tid;
    const int py = blockIdx.x;
    const int n  = blockIdx.y;
    const int y0 = 2 * py - 1;
    const int x0 = 2 * px - 1;

    float p[3][4][4];
    const bool interior = (px >= 1) & (px <= 254) & (py >= 1) & (py <= 254);
    if (interior) {
        const float* bp = x + (size_t)n * 3 * H0 * W0 + (size_t)y0 * W0 + x0;
#pragma unroll
        for (int c = 0; c < 3; ++c)
#pragma unroll
            for (int dy = 0; dy < 4; ++dy)
#pragma unroll
                for (int dx = 0; dx < 4; ++dx)
                    p[c][dy][dx] = __ldg(bp + c * (H0 * W0) + dy * W0 + dx);
    } else {
        const float* xn = x + (size_t)n * 3 * H0 * W0;
#pragma unroll
        for (int c = 0; c < 3; ++c) {
            const float* xc = xn + (size_t)c * H0 * W0;
#pragma unroll
            for (int dy = 0; dy < 4; ++dy) {
                const int y = y0 + dy;
                const bool yok = ((unsigned)y < (unsigned)H0);
#pragma unroll
                for (int dx = 0; dx < 4; ++dx) {
                    const int xx = x0 + dx;
                    p[c][dy][dx] = (yok && (unsigned)xx < (unsigned)W0)
                                       ? __ldg(xc + (size_t)y * W0 + xx) : 0.0f;
                }
            }
        }
    }

    float a00[4], a01[4], a10[4], a11[4];
#pragma unroll
    for (int co = 0; co < 4; ++co) {
        const float bb = sb[co];
        a00[co] = bb; a01[co] = bb; a10[co] = bb; a11[co] = bb;
    }

#pragma unroll
    for (int c = 0; c < 3; ++c)
#pragma unroll
        for (int ky = 0; ky < 3; ++ky)
#pragma unroll
            for (int kx = 0; kx < 3; ++kx) {
                const float4 w4 = sw4[c * 9 + ky * 3 + kx];
                const float t00 = p[c][ky    ][kx    ];
                const float t01 = p[c][ky    ][kx + 1];
                const float t10 = p[c][ky + 1][kx    ];
                const float t11 = p[c][ky + 1][kx + 1];
                a00[0] = fmaf(t00, w4.x, a00[0]); a00[1] = fmaf(t00, w4.y, a00[1]);
                a00[2] = fmaf(t00, w4.z, a00[2]); a00[3] = fmaf(t00, w4.w, a00[3]);
                a01[0] = fmaf(t01, w4.x, a01[0]); a01[1] = fmaf(t01, w4.y, a01[1]);
                a01[2] = fmaf(t01, w4.z, a01[2]); a01[3] = fmaf(t01, w4.w, a01[3]);
                a10[0] = fmaf(t10, w4.x, a10[0]); a10[1] = fmaf(t10, w4.y, a10[1]);
                a10[2] = fmaf(t10, w4.z, a10[2]); a10[3] = fmaf(t10, w4.w, a10[3]);
                a11[0] = fmaf(t11, w4.x, a11[0]); a11[1] = fmaf(t11, w4.y, a11[1]);
                a11[2] = fmaf(t11, w4.z, a11[2]); a11[3] = fmaf(t11, w4.w, a11[3]);
            }

    float res[4];
#pragma unroll
    for (int co = 0; co < 4; ++co)
        res[co] = 0.25f * (fmaxf(a00[co], 0.f) + fmaxf(a01[co], 0.f) +
                           fmaxf(a10[co], 0.f) + fmaxf(a11[co], 0.f));

    float4* o = (float4*)(g_h1 + (((size_t)n * H1 + py) * W1 + px) * 4);
    *o = make_float4(res[0], res[1], res[2], res[3]);
}

// ---------------------------------------------------------------------------
// Kernel 2: conv2(4->16, 3x3 SAME) + ReLU + 2x2 avgpool, NHWC -> NHWC
// One thread = one pooled pixel, co processed in 4 groups of 4.
// grid = (H2, NB), block = 128
// ---------------------------------------------------------------------------
__global__ void __launch_bounds__(W2) conv2_pool_kernel(
    const float* __restrict__ w,   // (16,4,3,3) co-major, 36 per co
    const float* __restrict__ b)
{
    __shared__ float4 sw4[4][36];  // [group][(ci*3+ky)*3+kx] -> w over 4 co in group
    __shared__ float  sb[16];
    const int tid = threadIdx.x;
    for (int i = tid; i < 144; i += W2) {
        const int g = i / 36, idx = i % 36;
        sw4[g][idx] = make_float4(w[(g * 4 + 0) * 36 + idx], w[(g * 4 + 1) * 36 + idx],
                                  w[(g * 4 + 2) * 36 + idx], w[(g * 4 + 3) * 36 + idx]);
    }
    if (tid < 16) sb[tid] = b[tid];
    __syncthreads();

    const int px = tid;
    const int py = blockIdx.x;
    const int n  = blockIdx.y;
    const int y0 = 2 * py - 1;
    const int x0 = 2 * px - 1;

    float p[4][4][4];  // [dy][dx][ci]
    const bool interior = (px >= 1) & (px <= 126) & (py >= 1) & (py <= 126);
    if (interior) {
        const float* bp = g_h1 + ((size_t)n * H1 * W1 + (size_t)y0 * W1 + x0) * 4;
#pragma unroll
        for (int dy = 0; dy < 4; ++dy)
#pragma unroll
            for (int dx = 0; dx < 4; ++dx) {
                const float4 t = *(const float4*)(bp + (dy * W1 + dx) * 4);
                p[dy][dx][0] = t.x; p[dy][dx][1] = t.y;
                p[dy][dx][2] = t.z; p[dy][dx][3] = t.w;
            }
    } else {
        const float* hn = g_h1 + (size_t)n * H1 * W1 * 4;
#pragma unroll
        for (int dy = 0; dy < 4; ++dy) {
            const int y = y0 + dy;
            const bool yok = ((unsigned)y < (unsigned)H1);
#pragma unroll
            for (int dx = 0; dx < 4; ++dx) {
                const int xx = x0 + dx;
                float4 t = make_float4(0.f, 0.f, 0.f, 0.f);
                if (yok && (unsigned)xx < (unsigned)W1)
                    t = *(const float4*)(hn + ((size_t)y * W1 + xx) * 4);
                p[dy][dx][0] = t.x; p[dy][dx][1] = t.y;
                p[dy][dx][2] = t.z; p[dy][dx][3] = t.w;
            }
        }
    }

    float res[16];
#pragma unroll
    for (int g = 0; g < 4; ++g) {
        float a00[4], a01[4], a10[4], a11[4];
#pragma unroll
        for (int j = 0; j < 4; ++j) {
            const float bb = sb[g * 4 + j];
            a00[j] = bb; a01[j] = bb; a10[j] = bb; a11[j] = bb;
        }
#pragma unroll
        for (int ci = 0; ci < 4; ++ci)
#pragma unroll
            for (int ky = 0; ky < 3; ++ky)
#pragma unroll
                for (int kx = 0; kx < 3; ++kx) {
                    const float4 w4 = sw4[g][(ci * 3 + ky) * 3 + kx];
                    const float t00 = p[ky    ][kx    ][ci];
                    const float t01 = p[ky    ][kx + 1][ci];
                    const float t10 = p[ky + 1][kx    ][ci];
                    const float t11 = p[ky + 1][kx + 1][ci];
                    a00[0] = fmaf(t00, w4.x, a00[0]); a00[1] = fmaf(t00, w4.y, a00[1]);
                    a00[2] = fmaf(t00, w4.z, a00[2]); a00[3] = fmaf(t00, w4.w, a00[3]);
                    a01[0] = fmaf(t01, w4.x, a01[0]); a01[1] = fmaf(t01, w4.y, a01[1]);
                    a01[2] = fmaf(t01, w4.z, a01[2]); a01[3] = fmaf(t01, w4.w, a01[3]);
                    a10[0] = fmaf(t10, w4.x, a10[0]); a10[1] = fmaf(t10, w4.y, a10[1]);
                    a10[2] = fmaf(t10, w4.z, a10[2]); a10[3] = fmaf(t10, w4.w, a10[3]);
                    a11[0] = fmaf(t11, w4.x, a11[0]); a11[1] = fmaf(t11, w4.y, a11[1]);
                    a11[2] = fmaf(t11, w4.z, a11[2]); a11[3] = fmaf(t11, w4.w, a11[3]);
                }
#pragma unroll
        for (int j = 0; j < 4; ++j)
            res[g * 4 + j] = 0.25f * (fmaxf(a00[j], 0.f) + fmaxf(a01[j], 0.f) +
                                      fmaxf(a10[j], 0.f) + fmaxf(a11[j], 0.f));
    }

    float4* o4 = (float4*)(g_h2 + ((size_t)n * MPIX + (size_t)py * W2 + px) * 16);
#pragma unroll
    for (int q = 0; q < 4; ++q)
        o4[q] = make_float4(res[q*4+0], res[q*4+1], res[q*4+2], res[q*4+3]);
}

// ---------------------------------------------------------------------------
// Kernel 3a: NetVLAD partial accumulation. grid=(NB, K3_CHUNKS), block=256
// ---------------------------------------------------------------------------
#define K3A_THREADS 256
__global__ void __launch_bounds__(K3A_THREADS) netvlad_partial_kernel(
    const float* __restrict__ aw, const float* __restrict__ ab)
{
    const int n   = blockIdx.x;
    const int ch  = blockIdx.y;
    const int tid = threadIdx.x;
    const int lane = tid & 31;
    const int wrp  = tid >> 5;

    __shared__ float s_aw[64];
    __shared__ float s_ab[4];
    if (tid < 64) s_aw[tid] = aw[tid];
    if (tid < 4)  s_ab[tid] = ab[tid];
    __syncthreads();

    float acc[68];
#pragma unroll
    for (int i = 0; i < 68; ++i) acc[i] = 0.0f;

    const int m0 = ch * (MPIX / K3_CHUNKS);
    const int m1 = m0 + (MPIX / K3_CHUNKS);
    const float* base = g_h2 + (size_t)n * MPIX * 16;
    for (int m = m0 + tid; m < m1; m += K3A_THREADS) {
        const float4* xp = (const float4*)(base + (size_t)m * 16);
        float xv[16];
#pragma unroll
        for (int q = 0; q < 4; ++q) {
            float4 v = xp[q];
            xv[q*4+0] = v.x; xv[q*4+1] = v.y; xv[q*4+2] = v.z; xv[q*4+3] = v.w;
        }
        float lg[4];
#pragma unroll
        for (int k = 0; k < 4; ++k) {
            float s = s_ab[k];
#pragma unroll
            for (int c = 0; c < 16; ++c) s = fmaf(xv[c], s_aw[k * 16 + c], s);
            lg[k] = s;
        }
        const float mx = fmaxf(fmaxf(lg[0], lg[1]), fmaxf(lg[2], lg[3]));
        float e[4], es = 0.0f;
#pragma unroll
        for (int k = 0; k < 4; ++k) { e[k] = __expf(lg[k] - mx); es += e[k]; }
        const float inv = __fdividef(1.0f, es);
#pragma unroll
        for (int k = 0; k < 4; ++k) {
            const float a = e[k] * inv;
            acc[64 + k] += a;
#pragma unroll
            for (int c = 0; c < 16; ++c)
                acc[k * 16 + c] = fmaf(a, xv[c], acc[k * 16 + c]);
        }
    }

#pragma unroll
    for (int off = 16; off > 0; off >>= 1)
#pragma unroll
        for (int i = 0; i < 68; ++i)
            acc[i] += __shfl_down_sync(0xffffffffu, acc[i], off);

    __shared__ float red[K3A_THREADS / 32][68];
    if (lane == 0)
#pragma unroll
        for (int i = 0; i < 68; ++i) red[wrp][i] = acc[i];
    __syncthreads();
    if (tid < 68) {
        float s = 0.0f;
#pragma unroll
        for (int ww = 0; ww < K3A_THREADS / 32; ++ww) s += red[ww][tid];
        g_part[n][ch][tid] = s;
    }
}

// ---------------------------------------------------------------------------
// Kernel 3b: finalize (norms + linear). grid=NB, block=128
// ---------------------------------------------------------------------------
__global__ void __launch_bounds__(128) netvlad_final_kernel(
    const float* __restrict__ cent,
    const float* __restrict__ lw,
    const float* __restrict__ lb,
    float* __restrict__ out)
{
    const int n = blockIdx.x;
    const int tid = threadIdx.x;

    __shared__ float sv[68];
    if (tid < 68) {
        float s = 0.0f;
#pragma unroll
        for (int ch = 0; ch < K3_CHUNKS; ++ch) s += g_part[n][ch][tid];
        sv[tid] = s;
    }
    __syncthreads();

    __shared__ float v2[64];
    __shared__ float nk[4];
    __shared__ float gn;
    if (tid < 64) {
        const int k = tid >> 4;
        v2[tid] = sv[tid] - sv[64 + k] * __ldg(cent + tid);
    }
    __syncthreads();
    if (tid < 4) {
        float s = 0.0f;
#pragma unroll
        for (int c = 0; c < 16; ++c) { const float v = v2[tid * 16 + c]; s = fmaf(v, v, s); }
        nk[tid] = fmaxf(sqrtf(s), 1e-12f);
    }
    __syncthreads();
    if (tid < 64) v2[tid] = v2[tid] / nk[tid >> 4];
    __syncthreads();
    if (tid == 0) {
        float s = 0.0f;
#pragma unroll
        for (int i = 0; i < 64; ++i) s = fmaf(v2[i], v2[i], s);
        gn = fmaxf(sqrtf(s), 1e-12f);
    }
    __syncthreads();
    if (tid < 7) {
        float s = __ldg(lb + tid);
        const float ig = 1.0f / gn;
#pragma unroll
        for (int i = 0; i < 64; ++i)
            s = fmaf(v2[i] * ig, __ldg(lw + tid * 64 + i), s);
        out[n * 7 + tid] = s;
    }
}

// ---------------------------------------------------------------------------
extern "C" void kernel_launch(void* const* d_in, const int* in_sizes, int n_in,
                              void* d_out, int out_size)
{
    (void)in_sizes; (void)n_in; (void)out_size;
    const float* x       = (const float*)d_in[0];
    const float* conv1_w = (const float*)d_in[1];
    const float* conv1_b = (const float*)d_in[2];
    const float* conv2_w = (const float*)d_in[3];
    const float* conv2_b = (const float*)d_in[4];
    const float* cent    = (const float*)d_in[5];
    const float* aw      = (const float*)d_in[6];
    const float* ab      = (const float*)d_in[7];
    const float* lw      = (const float*)d_in[8];
    const float* lb      = (const float*)d_in[9];
    float* out = (float*)d_out;

    dim3 g1(H1, NB); conv1_pool_kernel<<<g1, W1>>>(x, conv1_w, conv1_b);
    dim3 g2(H2, NB); conv2_pool_kernel<<<g2, W2>>>(conv2_w, conv2_b);
    dim3 g3(NB, K3_CHUNKS); netvlad_partial_kernel<<<g3, K3A_THREADS>>>(aw, ab);
    netvlad_final_kernel<<<NB, 128>>>(cent, lw, lb, out);
}